// round 7
// baseline (speedup 1.0000x reference)
#include <cuda_runtime.h>

// GlobalFilter: y = irfft2(rfft2(x, ortho) * W, ortho)
// x: [128,14,14,768] f32, W: [14,8,768,2] f32.
// R7: channel-pair packing. Each thread owns TWO adjacent channels; all
//     packed f32x2 ops carry (c0,c1). Global accesses 8B, smem slots 16B
//     (LDS.128/STS.128). R5 3-pass W-first structure, pass B in registers.

#define CC  768
#define NTH 256

typedef unsigned long long ull;

__device__ __forceinline__ ull pk(float lo, float hi) {
    ull r; asm("mov.b64 %0, {%1,%2};" : "=l"(r) : "f"(lo), "f"(hi)); return r;
}
__device__ __forceinline__ ull f2fma(ull a, ull b, ull c) {
    ull d; asm("fma.rn.f32x2 %0, %1, %2, %3;" : "=l"(d) : "l"(a), "l"(b), "l"(c)); return d;
}
__device__ __forceinline__ ull f2mul(ull a, ull b) {
    ull d; asm("mul.rn.f32x2 %0, %1, %2;" : "=l"(d) : "l"(a), "l"(b)); return d;
}
__device__ __forceinline__ ull f2add(ull a, ull b) {
    ull d; asm("add.rn.f32x2 %0, %1, %2;" : "=l"(d) : "l"(a), "l"(b)); return d;
}
__device__ __forceinline__ ull f2sub(ull a, ull b) {
    ull d; asm("sub.rn.f32x2 %0, %1, %2;" : "=l"(d) : "l"(a), "l"(b)); return d;
}
__host__ __device__ constexpr ull pkc(float lo, float hi) {
    return (ull)__builtin_bit_cast(unsigned int, lo)
         | ((ull)__builtin_bit_cast(unsigned int, hi) << 32);
}
#define CP(v) pkc(v, v)

#define DEF_TWIDDLES \
    constexpr float COS14[14] = { \
         1.0f,                 0.9009688679024191f,  0.6234898018587336f, \
         0.22252093395631445f,-0.22252093395631445f,-0.6234898018587336f, \
        -0.9009688679024191f, -1.0f,                -0.9009688679024191f, \
        -0.6234898018587336f, -0.22252093395631445f, 0.22252093395631445f, \
         0.6234898018587336f,  0.9009688679024191f }; \
    constexpr float SIN14[14] = { \
         0.0f,                 0.43388373911755823f, 0.7818314824680298f, \
         0.9749279121818236f,  0.9749279121818236f,  0.7818314824680298f, \
         0.43388373911755823f, 0.0f,                -0.43388373911755823f, \
        -0.7818314824680298f, -0.9749279121818236f, -0.9749279121818236f, \
        -0.7818314824680298f, -0.43388373911755823f }

__global__ __launch_bounds__(NTH, 3)
void gfilter_kernel(const float* __restrict__ x,
                    const float* __restrict__ wt,
                    float* __restrict__ y)
{
    DEF_TWIDDLES;
    // 112 slots x 32 channel-pairs, 16B each: {re(c0,c1), im(c0,c1)}
    extern __shared__ ulonglong2 sbuf[];

    const int tid  = threadIdx.x;
    const int p    = tid & 31;      // channel pair within CTA
    const int role = tid >> 5;      // 0..7, one warp per role
    const int b    = blockIdx.y;
    const int c0   = blockIdx.x * 64 + 2 * p;

    const int base = (b * 196) * CC + c0;       // even -> 8B aligned
    const ull* xb8 = reinterpret_cast<const ull*>(x + base);   // (c0,c1) pairs

    // ---- Pass A: rfft over W on rows from global ----------------------------
    #pragma unroll
    for (int i = 0; i < 2; ++i) {
        const int h = role + 8 * i;
        if (i == 0 || role < 6) {
            const ull x0 = xb8[(h * 14 + 0) * 384];
            const ull x7 = xb8[(h * 14 + 7) * 384];
            ull e[7], o[7];
            #pragma unroll
            for (int j = 1; j <= 6; ++j) {
                const ull a  = xb8[(h * 14 + j) * 384];
                const ull bq = xb8[(h * 14 + 14 - j) * 384];
                e[j] = f2add(a, bq);
                o[j] = f2sub(a, bq);
            }
            const ull be = f2add(x0, x7), bo = f2sub(x0, x7);
            #pragma unroll
            for (int kw = 0; kw < 8; ++kw) {
                ull re = (kw & 1) ? bo : be;
                ull im = 0ull;
                #pragma unroll
                for (int j = 1; j <= 6; ++j) {
                    const int m = (kw * j) % 14;
                    re = f2fma(e[j], CP(COS14[m]), re);
                    if ((m % 7) != 0)
                        im = f2fma(o[j], CP(-SIN14[m]), im);
                }
                sbuf[(h * 8 + kw) * 32 + p] = make_ulonglong2(re, im);
            }
        }
    }
    __syncthreads();

    // ---- Pass B: fwd H-DFT + weight + inv H-DFT, one kw column per warp ----
    {
        const int kw = role;
        ulonglong2* col = sbuf + p;             // index: (h*8+kw)*32

        // fold on load over h
        ull Ere[7], Eim[7], Ore[7], Oim[7];
        const ulonglong2 F0 = col[(0 * 8 + kw) * 32];
        const ulonglong2 F7 = col[(7 * 8 + kw) * 32];
        #pragma unroll
        for (int j = 1; j <= 6; ++j) {
            const ulonglong2 a  = col[(j * 8 + kw) * 32];
            const ulonglong2 bq = col[((14 - j) * 8 + kw) * 32];
            Ere[j] = f2add(a.x, bq.x);  Ore[j] = f2sub(a.x, bq.x);
            Eim[j] = f2add(a.y, bq.y);  Oim[j] = f2sub(a.y, bq.y);
        }
        const ull bpre = f2add(F0.x, F7.x), bmre = f2sub(F0.x, F7.x);
        const ull bpim = f2add(F0.y, F7.y), bmim = f2sub(F0.y, F7.y);

        const float4* wt4 = reinterpret_cast<const float4*>(wt)
                          + (size_t)(blockIdx.x * 16 + (p >> 1)) * 0; // (unused)
        const float4* wtp = reinterpret_cast<const float4*>(wt)
                          + blockIdx.x * 32 + p;   // + (row)*384 below
        (void)wt4;

        // forward per kh-pair, weight-multiply, write Z into own column slots
        #pragma unroll
        for (int kh = 0; kh < 8; ++kh) {
            ull Cre = (kh & 1) ? bmre : bpre;
            ull Cim = (kh & 1) ? bmim : bpim;
            ull Sre = 0ull, Sim = 0ull;
            #pragma unroll
            for (int j = 1; j <= 6; ++j) {
                const int m = (kh * j) % 14;
                Cre = f2fma(Ere[j], CP(COS14[m]), Cre);
                Cim = f2fma(Eim[j], CP(COS14[m]), Cim);
                if ((m % 7) != 0) {
                    Sre = f2fma(Ore[j], CP(SIN14[m]), Sre);
                    Sim = f2fma(Oim[j], CP(SIN14[m]), Sim);
                }
            }
            {   // X[kh] = C - iS -> (Cre+Sim, Cim-Sre), times weight
                const ull Xre = f2add(Cre, Sim);
                const ull Xim = f2sub(Cim, Sre);
                const float4 wv = wtp[(kh * 8 + kw) * 384];
                const ull wr = pk(wv.x, wv.z), wi = pk(wv.y, wv.w);
                col[(kh * 8 + kw) * 32] = make_ulonglong2(
                    f2sub(f2mul(Xre, wr), f2mul(Xim, wi)),
                    f2fma(Xim, wr, f2mul(Xre, wi)));
            }
            if (kh >= 1 && kh <= 6) {   // X[14-kh] = C + iS
                const ull Xre = f2sub(Cre, Sim);
                const ull Xim = f2add(Cim, Sre);
                const float4 wv = wtp[((14 - kh) * 8 + kw) * 384];
                const ull wr = pk(wv.x, wv.z), wi = pk(wv.y, wv.w);
                col[((14 - kh) * 8 + kw) * 32] = make_ulonglong2(
                    f2sub(f2mul(Xre, wr), f2mul(Xim, wi)),
                    f2fma(Xim, wr, f2mul(Xre, wi)));
            }
        }

        // inverse H-DFT: reload own column, fold, write Y1 back
        ull EZre[7], EZim[7], OZre[7], OZim[7];
        const ulonglong2 Z0 = col[(0 * 8 + kw) * 32];
        const ulonglong2 Z7 = col[(7 * 8 + kw) * 32];
        #pragma unroll
        for (int j = 1; j <= 6; ++j) {
            const ulonglong2 a  = col[(j * 8 + kw) * 32];
            const ulonglong2 bq = col[((14 - j) * 8 + kw) * 32];
            EZre[j] = f2add(a.x, bq.x);  OZre[j] = f2sub(a.x, bq.x);
            EZim[j] = f2add(a.y, bq.y);  OZim[j] = f2sub(a.y, bq.y);
        }
        const ull ipre = f2add(Z0.x, Z7.x), imre = f2sub(Z0.x, Z7.x);
        const ull ipim = f2add(Z0.y, Z7.y), imim = f2sub(Z0.y, Z7.y);
        #pragma unroll
        for (int h = 0; h < 8; ++h) {
            ull Cre = (h & 1) ? imre : ipre;
            ull Cim = (h & 1) ? imim : ipim;
            ull Sre = 0ull, Sim = 0ull;
            #pragma unroll
            for (int j = 1; j <= 6; ++j) {
                const int m = (j * h) % 14;
                Cre = f2fma(EZre[j], CP(COS14[m]), Cre);
                Cim = f2fma(EZim[j], CP(COS14[m]), Cim);
                if ((m % 7) != 0) {
                    Sre = f2fma(OZre[j], CP(SIN14[m]), Sre);
                    Sim = f2fma(OZim[j], CP(SIN14[m]), Sim);
                }
            }
            // Y = C + iS -> (Cre - Sim, Cim + Sre)
            col[(h * 8 + kw) * 32] = make_ulonglong2(f2sub(Cre, Sim), f2add(Cim, Sre));
            if (h >= 1 && h <= 6)
                col[((14 - h) * 8 + kw) * 32] =
                    make_ulonglong2(f2add(Cre, Sim), f2sub(Cim, Sre));
        }
    }
    __syncthreads();

    // ---- Pass C: c2r over W (w-paired) + ortho scale, write out ------------
    ull* yb8 = reinterpret_cast<ull*>(y + base);
    #pragma unroll
    for (int i = 0; i < 2; ++i) {
        const int h = role + 8 * i;
        if (i == 0 || role < 6) {
            ull Yre[8], Yim[8];
            #pragma unroll
            for (int kw = 0; kw < 8; ++kw) {
                const ulonglong2 v = sbuf[(h * 8 + kw) * 32 + p];
                Yre[kw] = v.x; Yim[kw] = v.y;
            }
            const ull h0 = f2mul(Yre[0], CP(0.5f));
            const ull h7 = f2mul(Yre[7], CP(0.5f));
            #pragma unroll
            for (int w = 0; w < 8; ++w) {
                ull C = 0ull, S = 0ull;
                #pragma unroll
                for (int kw = 1; kw <= 6; ++kw) {
                    const int m = (kw * w) % 14;
                    C = f2fma(Yre[kw], CP(COS14[m]), C);
                    if ((m % 7) != 0)
                        S = f2fma(Yim[kw], CP(SIN14[m]), S);
                }
                const ull bse = (w & 1) ? f2sub(h0, h7) : f2add(h0, h7);
                yb8[(h * 14 + w) * 384] =
                    f2mul(f2add(bse, f2sub(C, S)), CP(1.0f / 98.0f));
                if (w >= 1 && w <= 6)
                    yb8[(h * 14 + 14 - w) * 384] =
                        f2mul(f2add(bse, f2add(C, S)), CP(1.0f / 98.0f));
            }
        }
    }
}

extern "C" void kernel_launch(void* const* d_in, const int* in_sizes, int n_in,
                              void* d_out, int out_size)
{
    (void)in_sizes; (void)n_in; (void)out_size;
    const float* x  = (const float*)d_in[0];
    const float* wt = (const float*)d_in[1];
    float* y        = (float*)d_out;

    const int smem_bytes = 112 * 32 * (int)sizeof(ulonglong2); // 57344
    cudaFuncSetAttribute(gfilter_kernel,
                         cudaFuncAttributeMaxDynamicSharedMemorySize, smem_bytes);

    dim3 grid(CC / 64, 128); // (12, 128)
    gfilter_kernel<<<grid, NTH, smem_bytes>>>(x, wt, y);
}

// round 8
// speedup vs baseline: 1.1675x; 1.1675x over previous
#include <cuda_runtime.h>

// GlobalFilter: y = irfft2(rfft2(x, ortho) * W, ortho)
// x: [128,14,14,768] f32, W: [14,8,768,2] f32.
// R8 = R5 (best: 36.9us) + pass-C scale folded into compile-time constants
//      (drops 196 FMUL/channel) + streaming stores. No structural change.

#define CC  768
#define CB  32
#define NTH 256

typedef unsigned long long ull;

__device__ __forceinline__ ull pk(float lo, float hi) {
    ull r; asm("mov.b64 %0, {%1,%2};" : "=l"(r) : "f"(lo), "f"(hi)); return r;
}
__device__ __forceinline__ void upk(ull v, float& lo, float& hi) {
    asm("mov.b64 {%0,%1}, %2;" : "=f"(lo), "=f"(hi) : "l"(v));
}
__device__ __forceinline__ ull f2fma(ull a, ull b, ull c) {
    ull d; asm("fma.rn.f32x2 %0, %1, %2, %3;" : "=l"(d) : "l"(a), "l"(b), "l"(c)); return d;
}
__device__ __forceinline__ ull f2add(ull a, ull b) {
    ull d; asm("add.rn.f32x2 %0, %1, %2;" : "=l"(d) : "l"(a), "l"(b)); return d;
}
__device__ __forceinline__ ull f2sub(ull a, ull b) {
    ull d; asm("sub.rn.f32x2 %0, %1, %2;" : "=l"(d) : "l"(a), "l"(b)); return d;
}
__host__ __device__ constexpr ull pkc(float lo, float hi) {
    return (ull)__builtin_bit_cast(unsigned int, lo)
         | ((ull)__builtin_bit_cast(unsigned int, hi) << 32);
}
// complex multiply (packed X) by float2 weight
__device__ __forceinline__ ull cmulw(ull X, float2 w) {
    float xr, xi; upk(X, xr, xi);
    return pk(fmaf(-xi, w.y, xr * w.x), fmaf(xi, w.x, xr * w.y));
}
__device__ __forceinline__ void stcs(float* p, float v) {
    asm volatile("st.global.cs.f32 [%0], %1;" :: "l"(p), "f"(v) : "memory");
}

#define DEF_TWIDDLES \
    constexpr float COS14[14] = { \
         1.0f,                 0.9009688679024191f,  0.6234898018587336f, \
         0.22252093395631445f,-0.22252093395631445f,-0.6234898018587336f, \
        -0.9009688679024191f, -1.0f,                -0.9009688679024191f, \
        -0.6234898018587336f, -0.22252093395631445f, 0.22252093395631445f, \
         0.6234898018587336f,  0.9009688679024191f }; \
    constexpr float SIN14[14] = { \
         0.0f,                 0.43388373911755823f, 0.7818314824680298f, \
         0.9749279121818236f,  0.9749279121818236f,  0.7818314824680298f, \
         0.43388373911755823f, 0.0f,                -0.43388373911755823f, \
        -0.7818314824680298f, -0.9749279121818236f, -0.9749279121818236f, \
        -0.7818314824680298f, -0.43388373911755823f }

__global__ __launch_bounds__(NTH, 4)
void gfilter_kernel(const float* __restrict__ x,
                    const float* __restrict__ wt,
                    float* __restrict__ y)
{
    DEF_TWIDDLES;
    constexpr float INV98  = 1.0f / 98.0f;
    constexpr float INV196 = 1.0f / 196.0f;
    extern __shared__ ull sbuf[];   // 112 slots x 32 channels, 8B each

    const int tid  = threadIdx.x;
    const int cl   = tid & 31;
    const int role = tid >> 5;      // 0..7, one warp per role
    const int b    = blockIdx.y;
    const int c    = blockIdx.x * CB + cl;

    ull* bufc = sbuf + cl;          // index: slot*32; slot = h*8 + kw
    const int base = (b * 196) * CC + c;
    const float* xb = x + base;

    // ---- Pass A: rfft over W on rows read straight from global -------------
    #pragma unroll
    for (int i = 0; i < 2; ++i) {
        const int h = role + 8 * i;
        if (i == 0 || role < 6) {
            float xv[14];
            #pragma unroll
            for (int w = 0; w < 14; ++w)
                xv[w] = __ldg(&xb[(h * 14 + w) * CC]);
            ull eo[7];
            #pragma unroll
            for (int j = 1; j <= 6; ++j)
                eo[j] = pk(xv[j] + xv[14 - j], xv[j] - xv[14 - j]);
            const float be = xv[0] + xv[7], bo = xv[0] - xv[7];
            #pragma unroll
            for (int kw = 0; kw < 8; ++kw) {
                ull acc = pk((kw & 1) ? bo : be, 0.f);   // (re, im)
                #pragma unroll
                for (int j = 1; j <= 6; ++j) {
                    const int m = (kw * j) % 14;
                    acc = f2fma(eo[j], pkc(COS14[m], -SIN14[m]), acc);
                }
                bufc[(h * 8 + kw) * 32] = acc;
            }
        }
    }
    __syncthreads();

    // ---- Pass B: fwd H-DFT + weight + inv H-DFT, one kw column per warp ----
    {
        const int kw = role;
        ull F[14];
        #pragma unroll
        for (int h = 0; h < 14; ++h)
            F[h] = bufc[(h * 8 + kw) * 32];
        // forward folds over h
        ull E[7], O[7];
        #pragma unroll
        for (int j = 1; j <= 6; ++j) {
            E[j] = f2add(F[j], F[14 - j]);
            O[j] = f2sub(F[j], F[14 - j]);
        }
        const ull fbp = f2add(F[0], F[7]);
        const ull fbm = f2sub(F[0], F[7]);

        const float2* wt2c = reinterpret_cast<const float2*>(wt) + c;

        // forward per kh-pair, weight-multiply, fold for inverse on the fly
        ull X0, X7, EZ[7], OZ[7];
        #pragma unroll
        for (int kh = 0; kh < 8; ++kh) {
            ull Cacc = (kh & 1) ? fbm : fbp;  // (Cr, Ci)
            ull Sacc = 0ull;                  // (Sr, Si)
            #pragma unroll
            for (int j = 1; j <= 6; ++j) {
                const int m = (kh * j) % 14;
                Cacc = f2fma(E[j], pkc(COS14[m], COS14[m]), Cacc);
                if ((m % 7) != 0)
                    Sacc = f2fma(O[j], pkc(SIN14[m], SIN14[m]), Sacc);
            }
            float sr, si; upk(Sacc, sr, si);
            // X[kh] = C - iS ; X[14-kh] = C + iS
            ull Xa = f2add(Cacc, pk(si, -sr));
            Xa = cmulw(Xa, __ldg(&wt2c[(kh * 8 + kw) * CC]));
            if (kh == 0)      X0 = Xa;
            else if (kh == 7) X7 = Xa;
            else {
                ull Xb = f2add(Cacc, pk(-si, sr));
                Xb = cmulw(Xb, __ldg(&wt2c[((14 - kh) * 8 + kw) * CC]));
                EZ[kh] = f2add(Xa, Xb);
                OZ[kh] = f2sub(Xa, Xb);
            }
        }
        // inverse H-DFT (e^{+i}), h paired with 14-h; write back to same column
        const ull ibp = f2add(X0, X7);
        const ull ibm = f2sub(X0, X7);
        #pragma unroll
        for (int h = 0; h < 8; ++h) {
            ull Cacc = (h & 1) ? ibm : ibp;
            ull Sacc = 0ull;
            #pragma unroll
            for (int j = 1; j <= 6; ++j) {
                const int m = (j * h) % 14;
                Cacc = f2fma(EZ[j], pkc(COS14[m], COS14[m]), Cacc);
                if ((m % 7) != 0)
                    Sacc = f2fma(OZ[j], pkc(SIN14[m], SIN14[m]), Sacc);
            }
            float sr, si; upk(Sacc, sr, si);
            bufc[(h * 8 + kw) * 32] = f2add(Cacc, pk(-si, sr));
            if (h >= 1 && h <= 6)
                bufc[((14 - h) * 8 + kw) * 32] = f2add(Cacc, pk(si, -sr));
        }
    }
    __syncthreads();

    // ---- Pass C: c2r over W (w-paired), scale folded into constants --------
    float* yb = y + base;
    #pragma unroll
    for (int i = 0; i < 2; ++i) {
        const int h = role + 8 * i;
        if (i == 0 || role < 6) {
            ull yv[8];
            #pragma unroll
            for (int kw = 0; kw < 8; ++kw)
                yv[kw] = bufc[(h * 8 + kw) * 32];
            float yr0, yi0, yr7, yi7;
            upk(yv[0], yr0, yi0); upk(yv[7], yr7, yi7);
            const float b0 = yr0 * INV196, b7 = yr7 * INV196;
            const float bse_e = b0 + b7, bse_o = b0 - b7;
            #pragma unroll
            for (int w = 0; w < 8; ++w) {
                // acc = (C, S) with pre-scaled twiddles; seeded with base in C
                ull acc = pk((w & 1) ? bse_o : bse_e, 0.f);
                #pragma unroll
                for (int kw = 1; kw <= 6; ++kw) {
                    const int m = (kw * w) % 14;
                    acc = f2fma(yv[kw], pkc(COS14[m] * INV98, SIN14[m] * INV98), acc);
                }
                float Cv, Sv; upk(acc, Cv, Sv);
                stcs(&yb[(h * 14 + w) * CC], Cv - Sv);
                if (w >= 1 && w <= 6)
                    stcs(&yb[(h * 14 + 14 - w) * CC], Cv + Sv);
            }
        }
    }
}

extern "C" void kernel_launch(void* const* d_in, const int* in_sizes, int n_in,
                              void* d_out, int out_size)
{
    (void)in_sizes; (void)n_in; (void)out_size;
    const float* x  = (const float*)d_in[0];
    const float* wt = (const float*)d_in[1];
    float* y        = (float*)d_out;

    const int smem_bytes = 112 * CB * (int)sizeof(ull); // 28672
    dim3 grid(CC / CB, 128); // (24, 128)
    gfilter_kernel<<<grid, NTH, smem_bytes>>>(x, wt, y);
}